// round 1
// baseline (speedup 1.0000x reference)
#include <cuda_runtime.h>
#include <math.h>

#define B_  64
#define N_  4096
#define V_  21
#define S_  50
#define E_  64
#define H_  128
#define TM  32

// ---------------- static device scratch (no allocations allowed) ----------------
__device__ float g_h0[V_*H_];
__device__ float g_c0[V_*H_];
__device__ float g_ai[S_*H_];
__device__ float g_ao[S_*H_];
__device__ float g_au[S_*H_];
__device__ float g_af[S_*H_];
__device__ float g_Uit[H_*H_];
__device__ float g_Uft[H_*H_];
__device__ float g_Uot[H_*H_];
__device__ float g_Uut[H_*H_];
// ping-pong h/c buffers: A holds levels with m<=2048, B holds m<=1024
__device__ float g_HA[B_*2048*H_];
__device__ float g_CA[B_*2048*H_];
__device__ float g_HB[B_*1024*H_];
__device__ float g_CB[B_*1024*H_];

__device__ __forceinline__ float sigm(float x){ return 1.0f/(1.0f+expf(-x)); }

// ---------------- transpose U matrices once: Ut[k][col] = U[col][k] ----------------
__global__ void transpose_kernel(const float* __restrict__ Ui, const float* __restrict__ Uf,
                                 const float* __restrict__ Uo, const float* __restrict__ Uu){
  int t = blockIdx.y;
  const float* src = (t==0)?Ui:(t==1)?Uf:(t==2)?Uo:Uu;
  float* dst       = (t==0)?g_Uit:(t==1)?g_Uft:(t==2)?g_Uot:g_Uut;
  int idx = blockIdx.x*blockDim.x + threadIdx.x;   // 0..16383
  int k = idx >> 7, c = idx & 127;
  dst[k*H_ + c] = src[c*H_ + k];
}

// ---------------- precompute leaf tables (per vocab) and symbol tables ----------------
__global__ void tables_kernel(const float* __restrict__ emb, const float* __restrict__ sym_emb,
                              const float* __restrict__ Wp, const float* __restrict__ bp,
                              const float* __restrict__ Wi, const float* __restrict__ bi,
                              const float* __restrict__ Wf, const float* __restrict__ bf,
                              const float* __restrict__ Wo, const float* __restrict__ bo,
                              const float* __restrict__ Wu, const float* __restrict__ bu){
  __shared__ float se[E_];
  __shared__ float sx[H_];
  int h   = threadIdx.x;        // 0..127
  int idx = blockIdx.x;         // 0..V_+S_-1
  if (idx < V_) {
    int v = idx;
    if (h < E_) se[h] = emb[v*E_ + h];
    __syncthreads();
    float x = bp[h];
    #pragma unroll 8
    for (int e = 0; e < E_; e++) x += se[e]*Wp[h*E_ + e];
    sx[h] = x;
    __syncthreads();
    float ai_ = bi[h], ao_ = bo[h], au_ = bu[h];
    #pragma unroll 8
    for (int k = 0; k < H_; k++){
      float xv = sx[k];
      ai_ += xv*Wi[h*H_+k];
      ao_ += xv*Wo[h*H_+k];
      au_ += xv*Wu[h*H_+k];
    }
    float gi = sigm(ai_), go = sigm(ao_), gu = tanhf(au_);
    float c = gi*gu;
    g_c0[v*H_+h] = c;
    g_h0[v*H_+h] = go*tanhf(c);
  } else {
    int s = idx - V_;
    if (h < E_) se[h] = sym_emb[s*E_ + h];
    __syncthreads();
    float x = bp[h];
    #pragma unroll 8
    for (int e = 0; e < E_; e++) x += se[e]*Wp[h*E_ + e];
    sx[h] = x;
    __syncthreads();
    float ai_ = bi[h], ao_ = bo[h], au_ = bu[h], af_ = bf[h];
    #pragma unroll 8
    for (int k = 0; k < H_; k++){
      float xv = sx[k];
      ai_ += xv*Wi[h*H_+k];
      ao_ += xv*Wo[h*H_+k];
      au_ += xv*Wu[h*H_+k];
      af_ += xv*Wf[h*H_+k];
    }
    g_ai[s*H_+h] = ai_;
    g_ao[s*H_+h] = ao_;
    g_au[s*H_+h] = au_;
    g_af[s*H_+h] = af_;
  }
}

// ---------------- per-level tree combine ----------------
// Block = 32 nodes x 256 threads; thread (ty,tx): nodes ty*4..+3, cols tx*4..+3.
// Smem: sHT/sHL/sHR/sCL/sCR [32][128] + sU [128][128] (transposed) + sSym[32].

__device__ __forceinline__ void stageU(const float* __restrict__ Ut, float* sU, int tid){
  float4* d = (float4*)sU;
  const float4* s = (const float4*)Ut;
  #pragma unroll
  for (int i = 0; i < 16; i++) d[tid + i*256] = s[tid + i*256];
}

__device__ __forceinline__ void mm(const float* sSrc, const float* sU, int tx, int ty, float4 acc[4]){
  #pragma unroll
  for (int n = 0; n < 4; n++) acc[n] = make_float4(0.f,0.f,0.f,0.f);
  const float4* u4 = (const float4*)sU;
  const float4* s4 = (const float4*)sSrc;
  #pragma unroll 2
  for (int k4 = 0; k4 < 32; k4++){
    float4 hv[4];
    #pragma unroll
    for (int n = 0; n < 4; n++) hv[n] = s4[(ty*4+n)*32 + k4];
    #pragma unroll
    for (int kk = 0; kk < 4; kk++){
      float4 u = u4[(k4*4+kk)*32 + tx];
      #pragma unroll
      for (int n = 0; n < 4; n++){
        float h = (kk==0)?hv[n].x:(kk==1)?hv[n].y:(kk==2)?hv[n].z:hv[n].w;
        acc[n].x += h*u.x;
        acc[n].y += h*u.y;
        acc[n].z += h*u.z;
        acc[n].w += h*u.w;
      }
    }
  }
}

template<bool FIRST>
__global__ __launch_bounds__(256) void level_kernel(
    const int* __restrict__ tokens, const int* __restrict__ symbols,
    int m, int off, int srcIsA, int dstIsA)
{
  extern __shared__ float sm[];
  float* sHT = sm;
  float* sHL = sm + 1*TM*H_;
  float* sHR = sm + 2*TM*H_;
  float* sCL = sm + 3*TM*H_;
  float* sCR = sm + 4*TM*H_;
  float* sU  = sm + 5*TM*H_;
  int*   sSym = (int*)(sm + 5*TM*H_ + H_*H_);

  const float* Hin = srcIsA ? g_HA : g_HB;
  const float* Cin = srcIsA ? g_CA : g_CB;
  float* Hout = dstIsA ? g_HA : g_HB;
  float* Cout = dstIsA ? g_CA : g_CB;

  int tid = threadIdx.x;
  int nodeBase = blockIdx.x * TM;

  // load phase: gather hl/hr/cl/cr for 32 nodes (float4 over cols)
  const float4* Hin4 = (const float4*)Hin;
  const float4* Cin4 = (const float4*)Cin;
  #pragma unroll
  for (int it = 0; it < (TM*32)/256; it++){
    int idx = tid + it*256;            // 0..1023 : nl = idx/32, c4 = idx%32
    int nl = idx >> 5, c4 = idx & 31;
    int node = nodeBase + nl;
    int b = node / m, j = node - b*m;
    float4 hl, hr, cl, cr;
    if (FIRST) {
      int t0 = tokens[b*N_ + 2*j];
      int t1 = tokens[b*N_ + 2*j + 1];
      hl = ((const float4*)g_h0)[t0*32 + c4];
      hr = ((const float4*)g_h0)[t1*32 + c4];
      cl = ((const float4*)g_c0)[t0*32 + c4];
      cr = ((const float4*)g_c0)[t1*32 + c4];
    } else {
      int base4 = (b*(2*m) + 2*j)*32 + c4;
      hl = Hin4[base4];
      hr = Hin4[base4 + 32];
      cl = Cin4[base4];
      cr = Cin4[base4 + 32];
    }
    ((float4*)sHL)[idx] = hl;
    ((float4*)sHR)[idx] = hr;
    ((float4*)sCL)[idx] = cl;
    ((float4*)sCR)[idx] = cr;
    float4 ht = make_float4(hl.x+hr.x, hl.y+hr.y, hl.z+hr.z, hl.w+hr.w);
    ((float4*)sHT)[idx] = ht;
  }
  if (tid < TM){
    int node = nodeBase + tid;
    int b = node / m, j = node - b*m;
    sSym[tid] = symbols[b*(N_-1) + off + j];
  }
  __syncthreads();

  int tx = tid & 31, ty = tid >> 5;
  float4 acc[4];

  // ---- u gate: gu = tanh(au[sym] + ht @ Uu^T) ----
  stageU(g_Uut, sU, tid);
  __syncthreads();
  mm(sHT, sU, tx, ty, acc);
  float4 gu[4];
  #pragma unroll
  for (int n = 0; n < 4; n++){
    int s = sSym[ty*4+n];
    float4 a = ((const float4*)(g_au + s*H_))[tx];
    gu[n].x = tanhf(acc[n].x + a.x);
    gu[n].y = tanhf(acc[n].y + a.y);
    gu[n].z = tanhf(acc[n].z + a.z);
    gu[n].w = tanhf(acc[n].w + a.w);
  }

  // ---- i gate: cnew = sigm(ai + ht@Ui^T) * gu ----
  __syncthreads();
  stageU(g_Uit, sU, tid);
  __syncthreads();
  mm(sHT, sU, tx, ty, acc);
  float4 cnew[4];
  #pragma unroll
  for (int n = 0; n < 4; n++){
    int s = sSym[ty*4+n];
    float4 a = ((const float4*)(g_ai + s*H_))[tx];
    cnew[n].x = sigm(acc[n].x + a.x)*gu[n].x;
    cnew[n].y = sigm(acc[n].y + a.y)*gu[n].y;
    cnew[n].z = sigm(acc[n].z + a.z)*gu[n].z;
    cnew[n].w = sigm(acc[n].w + a.w)*gu[n].w;
  }

  // ---- f gates: cnew += sigm(af + hl@Uf^T)*cl + sigm(af + hr@Uf^T)*cr ----
  __syncthreads();
  stageU(g_Uft, sU, tid);
  __syncthreads();
  mm(sHL, sU, tx, ty, acc);
  #pragma unroll
  for (int n = 0; n < 4; n++){
    int s = sSym[ty*4+n];
    float4 a = ((const float4*)(g_af + s*H_))[tx];
    float4 cl = ((const float4*)(sCL + (ty*4+n)*H_))[tx];
    cnew[n].x += sigm(acc[n].x + a.x)*cl.x;
    cnew[n].y += sigm(acc[n].y + a.y)*cl.y;
    cnew[n].z += sigm(acc[n].z + a.z)*cl.z;
    cnew[n].w += sigm(acc[n].w + a.w)*cl.w;
  }
  mm(sHR, sU, tx, ty, acc);   // same staged Uf
  #pragma unroll
  for (int n = 0; n < 4; n++){
    int s = sSym[ty*4+n];
    float4 a = ((const float4*)(g_af + s*H_))[tx];
    float4 cr = ((const float4*)(sCR + (ty*4+n)*H_))[tx];
    cnew[n].x += sigm(acc[n].x + a.x)*cr.x;
    cnew[n].y += sigm(acc[n].y + a.y)*cr.y;
    cnew[n].z += sigm(acc[n].z + a.z)*cr.z;
    cnew[n].w += sigm(acc[n].w + a.w)*cr.w;
  }

  // ---- o gate: h = sigm(ao + ht@Uo^T) * tanh(cnew); write out ----
  __syncthreads();
  stageU(g_Uot, sU, tid);
  __syncthreads();
  mm(sHT, sU, tx, ty, acc);
  #pragma unroll
  for (int n = 0; n < 4; n++){
    int s = sSym[ty*4+n];
    float4 a = ((const float4*)(g_ao + s*H_))[tx];
    float4 hn;
    hn.x = sigm(acc[n].x + a.x)*tanhf(cnew[n].x);
    hn.y = sigm(acc[n].y + a.y)*tanhf(cnew[n].y);
    hn.z = sigm(acc[n].z + a.z)*tanhf(cnew[n].z);
    hn.w = sigm(acc[n].w + a.w)*tanhf(cnew[n].w);
    int node = nodeBase + ty*4 + n;
    ((float4*)Hout)[node*32 + tx] = hn;
    ((float4*)Cout)[node*32 + tx] = cnew[n];
  }
}

// ---------------- final projection: out = root_h @ Wout^T + bout ----------------
__global__ void out_kernel(const float* __restrict__ Wout, const float* __restrict__ bout,
                           float* __restrict__ out, int finalIsA){
  __shared__ float sh[H_];
  const float* Hfin = finalIsA ? g_HA : g_HB;
  int b = blockIdx.x, o = threadIdx.x;
  sh[o] = Hfin[b*H_ + o];
  __syncthreads();
  float acc = bout[o];
  #pragma unroll 8
  for (int k = 0; k < H_; k++) acc += sh[k]*Wout[o*H_ + k];
  out[b*H_ + o] = acc;
}

// ---------------- host orchestration ----------------
extern "C" void kernel_launch(void* const* d_in, const int* in_sizes, int n_in,
                              void* d_out, int out_size) {
  const int*   tokens  = (const int*)  d_in[0];
  const int*   symbols = (const int*)  d_in[1];
  const float* emb     = (const float*)d_in[2];
  const float* sym_emb = (const float*)d_in[3];
  const float* Wp   = (const float*)d_in[4];
  const float* bp   = (const float*)d_in[5];
  const float* Wi   = (const float*)d_in[6];
  const float* bi   = (const float*)d_in[7];
  const float* Ui   = (const float*)d_in[8];
  const float* Wf   = (const float*)d_in[9];
  const float* bf   = (const float*)d_in[10];
  const float* Uf   = (const float*)d_in[11];
  const float* Wo   = (const float*)d_in[12];
  const float* bo   = (const float*)d_in[13];
  const float* Uo   = (const float*)d_in[14];
  const float* Wu   = (const float*)d_in[15];
  const float* bu   = (const float*)d_in[16];
  const float* Uu   = (const float*)d_in[17];
  const float* Wout = (const float*)d_in[18];
  const float* bout = (const float*)d_in[19];

  int smemBytes = (5*TM*H_ + H_*H_)*(int)sizeof(float) + TM*(int)sizeof(int);
  cudaFuncSetAttribute(level_kernel<true>,  cudaFuncAttributeMaxDynamicSharedMemorySize, smemBytes);
  cudaFuncSetAttribute(level_kernel<false>, cudaFuncAttributeMaxDynamicSharedMemorySize, smemBytes);

  transpose_kernel<<<dim3(64,4), 256>>>(Ui, Uf, Uo, Uu);
  tables_kernel<<<V_+S_, H_>>>(emb, sym_emb, Wp, bp, Wi, bi, Wf, bf, Wo, bo, Wu, bu);

  int m = N_/2, off = 0;
  // level 0: gather leaves from token tables, write buffer A
  level_kernel<true><<<(B_*m)/TM, 256, smemBytes>>>(tokens, symbols, m, off, /*src*/1, /*dst*/1);
  off += m; m >>= 1;
  int srcA = 1, dstA = 0, lastDstA = 1;
  while (m >= 1){
    level_kernel<false><<<(B_*m)/TM, 256, smemBytes>>>(tokens, symbols, m, off, srcA, dstA);
    lastDstA = dstA;
    off += m; m >>= 1;
    srcA ^= 1; dstA ^= 1;
  }

  out_kernel<<<B_, H_>>>(Wout, bout, (float*)d_out, lastDstA);
}

// round 2
// speedup vs baseline: 1.9146x; 1.9146x over previous
#include <cuda_runtime.h>
#include <cuda_fp16.h>
#include <math.h>

#define B_ 64
#define N_ 4096
#define V_ 21
#define S_ 50
#define E_ 64
#define H_ 128
#define THREADS 512
#define NCTAS 148

#define PADH 136        // halves per padded smem row (272B, 16B aligned, conflict-free ldmatrix)
#define PADH2 68

// ---------------- static device scratch ----------------
__device__ __half g_U16[512*H_];   // rows 0-127 Ui, 128-255 Uo, 256-383 Uu, 384-511 Uf (row r = U[r][:])
__device__ float  g_tai[S_*H_], g_tao[S_*H_], g_tau[S_*H_], g_taf[S_*H_];
__device__ __half g_h016[V_*H_];
__device__ float  g_c0[V_*H_];
__device__ __half g_HA[B_*2048*H_];
__device__ __half g_HB[B_*1024*H_];
__device__ float  g_CA[B_*2048*H_];
__device__ float  g_CB[B_*1024*H_];
__device__ float  g_hroot[B_*H_];
__device__ unsigned g_bar;

__device__ __forceinline__ float sigmf_(float x){
  return __fdividef(1.f, 1.f + __expf(-x));
}
__device__ __forceinline__ float tanhf_(float x){
  return 2.f*__fdividef(1.f, 1.f + __expf(-2.f*x)) - 1.f;
}

// ---------------- prep: leaf/symbol tables ----------------
__global__ void tables_kernel(const float* __restrict__ emb, const float* __restrict__ sym_emb,
                              const float* __restrict__ Wp, const float* __restrict__ bp,
                              const float* __restrict__ Wi, const float* __restrict__ bi,
                              const float* __restrict__ Wf, const float* __restrict__ bf,
                              const float* __restrict__ Wo, const float* __restrict__ bo,
                              const float* __restrict__ Wu, const float* __restrict__ bu){
  __shared__ float se[E_];
  __shared__ float sx[H_];
  int h   = threadIdx.x;
  int idx = blockIdx.x;
  if (idx == 0 && h == 0) g_bar = 0u;
  if (idx < V_) {
    int v = idx;
    if (h < E_) se[h] = emb[v*E_ + h];
    __syncthreads();
    float x = bp[h];
    #pragma unroll 8
    for (int e = 0; e < E_; e++) x += se[e]*Wp[h*E_ + e];
    sx[h] = x;
    __syncthreads();
    float ai_ = bi[h], ao_ = bo[h], au_ = bu[h];
    #pragma unroll 8
    for (int k = 0; k < H_; k++){
      float xv = sx[k];
      ai_ += xv*Wi[h*H_+k];
      ao_ += xv*Wo[h*H_+k];
      au_ += xv*Wu[h*H_+k];
    }
    float gi = 1.f/(1.f+expf(-ai_)), go = 1.f/(1.f+expf(-ao_)), gu = tanhf(au_);
    float c = gi*gu;
    g_c0[v*H_+h] = c;
    g_h016[v*H_+h] = __float2half(go*tanhf(c));
  } else {
    int s = idx - V_;
    if (h < E_) se[h] = sym_emb[s*E_ + h];
    __syncthreads();
    float x = bp[h];
    #pragma unroll 8
    for (int e = 0; e < E_; e++) x += se[e]*Wp[h*E_ + e];
    sx[h] = x;
    __syncthreads();
    float ai_ = bi[h], ao_ = bo[h], au_ = bu[h], af_ = bf[h];
    #pragma unroll 8
    for (int k = 0; k < H_; k++){
      float xv = sx[k];
      ai_ += xv*Wi[h*H_+k];
      ao_ += xv*Wo[h*H_+k];
      au_ += xv*Wu[h*H_+k];
      af_ += xv*Wf[h*H_+k];
    }
    g_tai[s*H_+h] = ai_;
    g_tao[s*H_+h] = ao_;
    g_tau[s*H_+h] = au_;
    g_taf[s*H_+h] = af_;
  }
}

// ---------------- prep: fp16 U-concat ----------------
__global__ void prepU_kernel(const float* __restrict__ Ui, const float* __restrict__ Uo,
                             const float* __restrict__ Uu, const float* __restrict__ Uf){
  int idx = blockIdx.x*blockDim.x + threadIdx.x;     // 0..65535
  int r = idx >> 7, k = idx & 127;
  float v;
  if      (r < 128) v = Ui[r*H_ + k];
  else if (r < 256) v = Uo[(r-128)*H_ + k];
  else if (r < 384) v = Uu[(r-256)*H_ + k];
  else              v = Uf[(r-384)*H_ + k];
  g_U16[idx] = __float2half(v);
}

// ---------------- mma helpers ----------------
__device__ __forceinline__ unsigned saddr(const void* p){
  return (unsigned)__cvta_generic_to_shared(p);
}
__device__ __forceinline__ void ldsm4(unsigned addr, unsigned &r0, unsigned &r1, unsigned &r2, unsigned &r3){
  asm volatile("ldmatrix.sync.aligned.m8n8.x4.shared.b16 {%0,%1,%2,%3}, [%4];"
    : "=r"(r0),"=r"(r1),"=r"(r2),"=r"(r3) : "r"(addr));
}
__device__ __forceinline__ void mma16816(float d[4], const unsigned a[4], unsigned b0, unsigned b1){
  asm volatile("mma.sync.aligned.m16n8k16.row.col.f32.f16.f16.f32 "
    "{%0,%1,%2,%3}, {%4,%5,%6,%7}, {%8,%9}, {%0,%1,%2,%3};"
    : "+f"(d[0]),"+f"(d[1]),"+f"(d[2]),"+f"(d[3])
    : "r"(a[0]),"r"(a[1]),"r"(a[2]),"r"(a[3]), "r"(b0),"r"(b1));
}

// ---------------- persistent tree kernel ----------------
// grid = 148 CTAs, 512 threads (16 warps: wm=wid/4 rows, wn=wid%4 cols)
// per tile: 64 nodes. GEMM1: ht[64x128] @ Uiou[384x128]^T. GEMM2: [hl;hr][128x128] @ Uf^T.
extern __shared__ __half smem_[];
__global__ __launch_bounds__(THREADS, 1) void tree_kernel(
  const int* __restrict__ tokens, const int* __restrict__ symbols,
  const float* __restrict__ Wout, const float* __restrict__ bout,
  float* __restrict__ out)
{
  __half* sB  = smem_;                 // 512 x PADH
  __half* sHT = sB + 512*PADH;         // 64 x PADH
  __half* sLR = sHT + 64*PADH;         // 128 x PADH (rows 0-63 hl, 64-127 hr)
  int* sSym   = (int*)(sLR + 128*PADH);
  int* sIdx0  = sSym + 64;
  int* sIdx1  = sIdx0 + 64;

  const int tid  = threadIdx.x;
  const int lane = tid & 31, wid = tid >> 5;
  const int wm   = wid >> 2, wn = wid & 3;

  // stage U (shared across all levels) once
  {
    const __half2* src = (const __half2*)g_U16;
    __half2* dst = (__half2*)sB;
    for (int idx = tid; idx < 512*64; idx += THREADS){
      int r = idx >> 6, k2 = idx & 63;
      dst[r*PADH2 + k2] = src[idx];
    }
  }
  __syncthreads();

  int m = 2048, off = 0;
  for (int lvl = 0; lvl < 12; lvl++){
    const __half* Hsrc; const float* Csrc;
    __half* Hdst; float* Cdst;
    if (lvl == 0)      { Hsrc = g_h016; Csrc = g_c0; }
    else if (lvl & 1)  { Hsrc = g_HA;   Csrc = g_CA; }
    else               { Hsrc = g_HB;   Csrc = g_CB; }
    if (lvl & 1) { Hdst = g_HB; Cdst = g_CB; } else { Hdst = g_HA; Cdst = g_CA; }

    const int tiles = (B_ * m) >> 6;
    const int logm  = 31 - __clz(m);

    for (int t = blockIdx.x; t < tiles; t += NCTAS){
      const int node0 = t << 6;
      // index phase
      if (tid < 64){
        int n_g = node0 + tid;
        int b = n_g >> logm, j = n_g & (m-1);
        sSym[tid] = symbols[b*(N_-1) + off + j];
        if (lvl == 0){
          sIdx0[tid] = tokens[b*N_ + 2*j];
          sIdx1[tid] = tokens[b*N_ + 2*j + 1];
        } else {
          sIdx0[tid] = 2*n_g;
          sIdx1[tid] = 2*n_g + 1;
        }
      }
      __syncthreads();
      // A staging: hl/hr rows + ht = hl+hr
      {
        const __half2* hs = (const __half2*)Hsrc;
        __half2* ht2 = (__half2*)sHT;
        __half2* lr2 = (__half2*)sLR;
        for (int idx = tid; idx < 64*64; idx += THREADS){
          int r = idx >> 6, k2 = idx & 63;
          __half2 a  = hs[sIdx0[r]*64 + k2];
          __half2 b2 = hs[sIdx1[r]*64 + k2];
          lr2[r*PADH2 + k2]        = a;
          lr2[(64 + r)*PADH2 + k2] = b2;
          ht2[r*PADH2 + k2] = __hadd2(a, b2);
        }
      }
      __syncthreads();

      // -------- GEMMs --------
      float acc1[12][4];  // [g*4+s]: gate g in {i,o,u}, col-subtile s
      float acc2[8][4];   // [s]: fl, [4+s]: fr
      #pragma unroll
      for (int i = 0; i < 12; i++){ acc1[i][0]=0.f; acc1[i][1]=0.f; acc1[i][2]=0.f; acc1[i][3]=0.f; }
      #pragma unroll
      for (int i = 0; i < 8; i++){ acc2[i][0]=0.f; acc2[i][1]=0.f; acc2[i][2]=0.f; acc2[i][3]=0.f; }

      #pragma unroll
      for (int k16 = 0; k16 < 8; k16++){
        const int kh = k16*16;
        const int arow = 16*wm + (lane & 15);
        const int acol = kh + (lane >> 4)*8;
        unsigned aT[4], aL[4], aR[4];
        ldsm4(saddr(&sHT[arow*PADH + acol]),        aT[0],aT[1],aT[2],aT[3]);
        ldsm4(saddr(&sLR[arow*PADH + acol]),        aL[0],aL[1],aL[2],aL[3]);
        ldsm4(saddr(&sLR[(64+arow)*PADH + acol]),   aR[0],aR[1],aR[2],aR[3]);

        const int brow_in = ((lane>>4)&1)*8 + (lane&7);
        const int bcol    = kh + ((lane>>3)&1)*8;
        #pragma unroll
        for (int g = 0; g < 3; g++){
          #pragma unroll
          for (int sp = 0; sp < 2; sp++){
            int R0 = 128*g + 32*wn + 16*sp;
            unsigned r0,r1,r2,r3;
            ldsm4(saddr(&sB[(R0 + brow_in)*PADH + bcol]), r0,r1,r2,r3);
            mma16816(acc1[g*4 + 2*sp + 0], aT, r0, r1);
            mma16816(acc1[g*4 + 2*sp + 1], aT, r2, r3);
          }
        }
        #pragma unroll
        for (int sp = 0; sp < 2; sp++){
          int R0 = 384 + 32*wn + 16*sp;
          unsigned r0,r1,r2,r3;
          ldsm4(saddr(&sB[(R0 + brow_in)*PADH + bcol]), r0,r1,r2,r3);
          mma16816(acc2[2*sp + 0], aL, r0, r1);
          mma16816(acc2[2*sp + 1], aL, r2, r3);
          mma16816(acc2[4 + 2*sp + 0], aR, r0, r1);
          mma16816(acc2[4 + 2*sp + 1], aR, r2, r3);
        }
      }

      // -------- epilogue --------
      const int cpair = (lane & 3)*2;
      #pragma unroll
      for (int half = 0; half < 2; half++){
        int rloc = (lane >> 2) + half*8;
        int nl = 16*wm + rloc;
        int n_g = node0 + nl;
        int sym = sSym[nl];
        int i0 = sIdx0[nl], i1 = sIdx1[nl];
        const float2* cl2p = (const float2*)(Csrc + i0*H_);
        const float2* cr2p = (const float2*)(Csrc + i1*H_);
        const float2* ai2  = (const float2*)(g_tai + sym*H_);
        const float2* ao2  = (const float2*)(g_tao + sym*H_);
        const float2* au2  = (const float2*)(g_tau + sym*H_);
        const float2* af2  = (const float2*)(g_taf + sym*H_);
        float2*  co = (float2*)(Cdst + n_g*H_);
        __half2* ho = (__half2*)(Hdst + n_g*H_);
        const int e = 2*half;
        #pragma unroll
        for (int s = 0; s < 4; s++){
          int c  = 32*wn + 8*s + cpair;
          int c2 = c >> 1;
          float2 ta = __ldg(ai2 + c2), to = __ldg(ao2 + c2);
          float2 tu = __ldg(au2 + c2), tf = __ldg(af2 + c2);
          float2 cl = __ldg(cl2p + c2), cr = __ldg(cr2p + c2);
          float pi0 = acc1[0*4+s][e]   + ta.x, pi1 = acc1[0*4+s][e+1] + ta.y;
          float po0 = acc1[1*4+s][e]   + to.x, po1 = acc1[1*4+s][e+1] + to.y;
          float pu0 = acc1[2*4+s][e]   + tu.x, pu1 = acc1[2*4+s][e+1] + tu.y;
          float fl0 = acc2[s][e]       + tf.x, fl1 = acc2[s][e+1]     + tf.y;
          float fr0 = acc2[4+s][e]     + tf.x, fr1 = acc2[4+s][e+1]   + tf.y;
          float cn0 = sigmf_(pi0)*tanhf_(pu0) + sigmf_(fl0)*cl.x + sigmf_(fr0)*cr.x;
          float cn1 = sigmf_(pi1)*tanhf_(pu1) + sigmf_(fl1)*cl.y + sigmf_(fr1)*cr.y;
          float h0 = sigmf_(po0)*tanhf_(cn0);
          float h1 = sigmf_(po1)*tanhf_(cn1);
          co[c2] = make_float2(cn0, cn1);
          ho[c2] = __floats2half2_rn(h0, h1);
          if (m == 1){
            ((float2*)(g_hroot + n_g*H_))[c2] = make_float2(h0, h1);
          }
        }
      }
      __syncthreads();   // smem reuse next tile
    }

    // grid-wide barrier between levels
    __syncthreads();
    if (tid == 0){
      __threadfence();
      atomicAdd(&g_bar, 1u);
      const unsigned target = (unsigned)(NCTAS*(lvl+1));
      while (atomicAdd(&g_bar, 0u) < target) __nanosleep(64);
      __threadfence();
    }
    __syncthreads();
    off += m; m >>= 1;
  }

  // final projection: out = hroot @ Wout^T + bout  (fp32)
  if (blockIdx.x == 0){
    for (int idx = tid; idx < B_*H_; idx += THREADS){
      int b = idx >> 7, o = idx & 127;
      float acc = bout[o];
      const float* w  = Wout + o*H_;
      const float* hr = g_hroot + b*H_;
      #pragma unroll 8
      for (int k = 0; k < H_; k++) acc += hr[k]*w[k];
      out[idx] = acc;
    }
  }
}

// ---------------- host orchestration ----------------
extern "C" void kernel_launch(void* const* d_in, const int* in_sizes, int n_in,
                              void* d_out, int out_size) {
  const int*   tokens  = (const int*)  d_in[0];
  const int*   symbols = (const int*)  d_in[1];
  const float* emb     = (const float*)d_in[2];
  const float* sym_emb = (const float*)d_in[3];
  const float* Wp   = (const float*)d_in[4];
  const float* bp   = (const float*)d_in[5];
  const float* Wi   = (const float*)d_in[6];
  const float* bi   = (const float*)d_in[7];
  const float* Ui   = (const float*)d_in[8];
  const float* Wf   = (const float*)d_in[9];
  const float* bf   = (const float*)d_in[10];
  const float* Uf   = (const float*)d_in[11];
  const float* Wo   = (const float*)d_in[12];
  const float* bo   = (const float*)d_in[13];
  const float* Uo   = (const float*)d_in[14];
  const float* Wu   = (const float*)d_in[15];
  const float* bu   = (const float*)d_in[16];
  const float* Uu   = (const float*)d_in[17];
  const float* Wout = (const float*)d_in[18];
  const float* bout = (const float*)d_in[19];

  const int smemBytes = (512 + 64 + 128)*PADH*(int)sizeof(__half) + 3*64*(int)sizeof(int);
  cudaFuncSetAttribute(tree_kernel, cudaFuncAttributeMaxDynamicSharedMemorySize, smemBytes);

  tables_kernel<<<V_ + S_, H_>>>(emb, sym_emb, Wp, bp, Wi, bi, Wf, bf, Wo, bo, Wu, bu);
  prepU_kernel<<<256, 256>>>(Ui, Uo, Uu, Uf);
  tree_kernel<<<NCTAS, THREADS, smemBytes>>>(tokens, symbols, Wout, bout, (float*)d_out);
}